// round 6
// baseline (speedup 1.0000x reference)
#include <cuda_runtime.h>
#include <math.h>

// Problem dims
#define Bq  32
#define Sq  512
#define Dq  512
#define Hq  8
#define Lq  4
#define Fq  2048
#define DKq 64
#define Mq  (Bq*Sq)   // 16384 rows

// ---------------- scratch (static __device__, no allocation) ----------------
__device__ float g_x  [Mq*Dq];
__device__ float g_y  [Mq*Dq];
__device__ float g_kq [Mq*Dq];
__device__ float g_kqt[Mq*Dq];   // (B,H,DK,S)
__device__ float g_v  [Mq*Dq];
__device__ float g_ctx[Mq*Dq];
__device__ float g_tmp[Mq*Dq];
__device__ float g_h1 [Mq*Fq];

// ---------------- x = q + pos ; y = qa + pos ----------------
__global__ void add_pos_kernel(const float4* __restrict__ q,
                               const float4* __restrict__ qa,
                               const float4* __restrict__ pos,
                               float4* __restrict__ x, float4* __restrict__ y)
{
    int i  = blockIdx.x * blockDim.x + threadIdx.x;   // Mq*Dq/4 total
    int pi = i & (Sq*Dq/4 - 1);                       // S*D/4 is pow2
    float4 p = pos[pi];
    float4 a = q[i];
    a.x += p.x; a.y += p.y; a.z += p.z; a.w += p.w;
    x[i] = a;
    float4 c = qa[i];
    c.x += p.x; c.y += p.y; c.z += p.z; c.w += p.w;
    y[i] = c;
}

// ---------------- SGEMM: C[M,N] = A[M,K] * W[N,K]^T + bias (opt ReLU) -------
// BM=BN=128, BK=16, 256 threads, 8x8 per thread.
// Double-buffered smem (ping-pong): one __syncthreads per k-tile; global
// loads for tile k+1 issued before the FFMA block of tile k.
// Vectorized float4 epilogue with hoisted bias.
// Requires M,N % 128 == 0 and K % 16 == 0.
template<bool RELU>
__global__ __launch_bounds__(256)
void sgemm_tn(const float* __restrict__ A, const float* __restrict__ W,
              const float* __restrict__ bias, float* __restrict__ C,
              int M, int N, int K)
{
    __shared__ float As[2][16][128];
    __shared__ float Ws[2][16][128];
    const int tid  = threadIdx.x;
    const int bm   = blockIdx.y * 128;
    const int bn   = blockIdx.x * 128;
    const int lrow = tid >> 1;          // 0..127
    const int lcol = (tid & 1) * 8;     // 0 or 8
    const float* Ag = A + (size_t)(bm + lrow) * K + lcol;
    const float* Wg = W + (size_t)(bn + lrow) * K + lcol;
    const int tx = tid & 15;            // col group
    const int ty = tid >> 4;            // row group

    float acc[8][8];
    #pragma unroll
    for (int i = 0; i < 8; i++)
        #pragma unroll
        for (int j = 0; j < 8; j++) acc[i][j] = 0.f;

    // preload tile 0 into smem buffer 0
    {
        float4 a0 = *(const float4*)(Ag);
        float4 a1 = *(const float4*)(Ag + 4);
        float4 w0 = *(const float4*)(Wg);
        float4 w1 = *(const float4*)(Wg + 4);
        As[0][lcol+0][lrow] = a0.x; As[0][lcol+1][lrow] = a0.y;
        As[0][lcol+2][lrow] = a0.z; As[0][lcol+3][lrow] = a0.w;
        As[0][lcol+4][lrow] = a1.x; As[0][lcol+5][lrow] = a1.y;
        As[0][lcol+6][lrow] = a1.z; As[0][lcol+7][lrow] = a1.w;
        Ws[0][lcol+0][lrow] = w0.x; Ws[0][lcol+1][lrow] = w0.y;
        Ws[0][lcol+2][lrow] = w0.z; Ws[0][lcol+3][lrow] = w0.w;
        Ws[0][lcol+4][lrow] = w1.x; Ws[0][lcol+5][lrow] = w1.y;
        Ws[0][lcol+6][lrow] = w1.z; Ws[0][lcol+7][lrow] = w1.w;
    }
    __syncthreads();

    int cur = 0;
    for (int k0 = 0; k0 < K; k0 += 16) {
        float4 a0, a1, w0, w1;
        const bool more = (k0 + 16 < K);
        if (more) {                     // issue next tile's LDGs early
            a0 = *(const float4*)(Ag + k0 + 16);
            a1 = *(const float4*)(Ag + k0 + 20);
            w0 = *(const float4*)(Wg + k0 + 16);
            w1 = *(const float4*)(Wg + k0 + 20);
        }
        #pragma unroll
        for (int k = 0; k < 16; k++) {
            float am[8], wn[8];
            #pragma unroll
            for (int i = 0; i < 8; i++) am[i] = As[cur][k][ty*8 + i];
            #pragma unroll
            for (int j = 0; j < 8; j++) wn[j] = Ws[cur][k][tx*8 + j];
            #pragma unroll
            for (int i = 0; i < 8; i++)
                #pragma unroll
                for (int j = 0; j < 8; j++)
                    acc[i][j] += am[i] * wn[j];
        }
        if (more) {
            int nxt = cur ^ 1;
            As[nxt][lcol+0][lrow] = a0.x; As[nxt][lcol+1][lrow] = a0.y;
            As[nxt][lcol+2][lrow] = a0.z; As[nxt][lcol+3][lrow] = a0.w;
            As[nxt][lcol+4][lrow] = a1.x; As[nxt][lcol+5][lrow] = a1.y;
            As[nxt][lcol+6][lrow] = a1.z; As[nxt][lcol+7][lrow] = a1.w;
            Ws[nxt][lcol+0][lrow] = w0.x; Ws[nxt][lcol+1][lrow] = w0.y;
            Ws[nxt][lcol+2][lrow] = w0.z; Ws[nxt][lcol+3][lrow] = w0.w;
            Ws[nxt][lcol+4][lrow] = w1.x; Ws[nxt][lcol+5][lrow] = w1.y;
            Ws[nxt][lcol+6][lrow] = w1.z; Ws[nxt][lcol+7][lrow] = w1.w;
            __syncthreads();
            cur = nxt;
        }
    }

    // epilogue: bias hoisted (2x LDG.128), stores as 2x STG.128 per row
    float4 bv0 = *(const float4*)(bias + bn + tx*8);
    float4 bv1 = *(const float4*)(bias + bn + tx*8 + 4);
    #pragma unroll
    for (int i = 0; i < 8; i++) {
        int m = bm + ty*8 + i;
        float* crow = C + (size_t)m * N + bn + tx*8;
        float4 o0, o1;
        o0.x = acc[i][0] + bv0.x; o0.y = acc[i][1] + bv0.y;
        o0.z = acc[i][2] + bv0.z; o0.w = acc[i][3] + bv0.w;
        o1.x = acc[i][4] + bv1.x; o1.y = acc[i][5] + bv1.y;
        o1.z = acc[i][6] + bv1.z; o1.w = acc[i][7] + bv1.w;
        if (RELU) {
            o0.x = fmaxf(o0.x, 0.f); o0.y = fmaxf(o0.y, 0.f);
            o0.z = fmaxf(o0.z, 0.f); o0.w = fmaxf(o0.w, 0.f);
            o1.x = fmaxf(o1.x, 0.f); o1.y = fmaxf(o1.y, 0.f);
            o1.z = fmaxf(o1.z, 0.f); o1.w = fmaxf(o1.w, 0.f);
        }
        *(float4*)(crow)     = o0;
        *(float4*)(crow + 4) = o1;
    }
}

// ---------------- transpose kq -> (B,H,DK,S) for coalesced key reads --------
__global__ void transpose_kq_kernel(const float* __restrict__ kq,
                                    float* __restrict__ kqt)
{
    __shared__ float tile[32][33];
    int bh = blockIdx.z;               // 0..B*H-1
    int dt = blockIdx.y;               // 0..DK/32-1
    int tt = blockIdx.x;               // 0..S/32-1
    int b = bh / Hq, h = bh % Hq;
    int tx = threadIdx.x;              // 32
    int ty = threadIdx.y;              // 8
    #pragma unroll
    for (int i = 0; i < 4; i++) {
        int t = tt*32 + ty + i*8;
        tile[ty + i*8][tx] = kq[((size_t)(b*Sq + t))*Dq + h*DKq + dt*32 + tx];
    }
    __syncthreads();
    #pragma unroll
    for (int i = 0; i < 4; i++) {
        int d = dt*32 + ty + i*8;
        kqt[((size_t)bh*DKq + d)*Sq + tt*32 + tx] = tile[tx][ty + i*8];
    }
}

// ---------------- two-pass strictly-causal attention ------------------------
// scores[s,t] = (kq[s] . kq[t]) * scale * fr[b,s],  allowed t < s, row 0 -> 0
// One warp per query row; at most 16 score-blocks (S=512) kept in registers:
// pass 1 computes scores + lane-local max, single warp max-reduce, pass 2
// does one exp per score and accumulates V; single sum-reduce at the end.
#define ATTN_WARPS 8
#define ROWSPLIT   4
#define NBLK  (Sq/32)    // 16
__global__ __launch_bounds__(ATTN_WARPS*32)
void attn_kernel(const float* __restrict__ kq, const float* __restrict__ kqt,
                 const float* __restrict__ v, const float* __restrict__ fr,
                 float* __restrict__ ctx)
{
    __shared__ float qs_all[ATTN_WARPS][64];
    int warp = threadIdx.x >> 5;
    int lane = threadIdx.x & 31;
    int bh   = blockIdx.x;
    int b = bh / Hq, h = bh % Hq;
    float* qs = qs_all[warp];
    const float scale = 0.125f;                       // 1/sqrt(64)
    const size_t base  = ((size_t)b * Sq) * Dq + h * DKq;   // (b,*,h) in (B,S,D)
    const float* KT = kqt + (size_t)bh * DKq * Sq;          // (DK,S)

    int sstart = blockIdx.y * ATTN_WARPS + warp;
    for (int s = sstart; s < Sq; s += ATTN_WARPS * ROWSPLIT) {
        size_t orow = base + (size_t)s * Dq;
        if (s == 0) {
            ctx[orow + lane] = 0.f; ctx[orow + lane + 32] = 0.f;
            continue;
        }
        float qsc = scale * fr[b*Sq + s];
        qs[lane]      = kq[orow + lane]      * qsc;
        qs[lane + 32] = kq[orow + lane + 32] * qsc;
        __syncwarp();

        // ---- pass 1: scores into registers, lane-local max ----
        float preg[NBLK];
        float mymax = -3.0e38f;
        #pragma unroll
        for (int ib = 0; ib < NBLK; ib++) {
            int t0 = ib * 32;
            if (t0 >= s) break;
            int t = t0 + lane;
            float sc = -3.0e38f;
            if (t < s) {
                const float* KTt = KT + t;
                float a0 = 0.f, a1 = 0.f, a2 = 0.f, a3 = 0.f;
                #pragma unroll
                for (int d = 0; d < 64; d += 4) {
                    a0 += qs[d+0] * KTt[(size_t)(d+0)*Sq];
                    a1 += qs[d+1] * KTt[(size_t)(d+1)*Sq];
                    a2 += qs[d+2] * KTt[(size_t)(d+2)*Sq];
                    a3 += qs[d+3] * KTt[(size_t)(d+3)*Sq];
                }
                sc = (a0 + a1) + (a2 + a3);
            }
            preg[ib] = sc;
            mymax = fmaxf(mymax, sc);
        }
        // single warp max-reduce
        #pragma unroll
        for (int off = 16; off; off >>= 1)
            mymax = fmaxf(mymax, __shfl_xor_sync(0xffffffffu, mymax, off));

        // ---- pass 2: exp + V accumulation ----
        float lsum = 0.f, o0 = 0.f, o1 = 0.f;
        #pragma unroll
        for (int ib = 0; ib < NBLK; ib++) {
            int t0 = ib * 32;
            if (t0 >= s) break;
            int t = t0 + lane;
            float p = (t < s) ? __expf(preg[ib] - mymax) : 0.f;
            lsum += p;
            int cnt = min(32, s - t0);
            const float* vb = v + base + (size_t)t0 * Dq;
            for (int tt = 0; tt < cnt; tt++) {
                float pt = __shfl_sync(0xffffffffu, p, tt);
                o0 += pt * vb[(size_t)tt * Dq + lane];
                o1 += pt * vb[(size_t)tt * Dq + lane + 32];
            }
        }
        // single warp sum-reduce
        #pragma unroll
        for (int off = 16; off; off >>= 1)
            lsum += __shfl_xor_sync(0xffffffffu, lsum, off);

        float inv = 1.f / lsum;
        ctx[orow + lane]      = o0 * inv;
        ctx[orow + lane + 32] = o1 * inv;
        __syncwarp();
    }
}

// ---------------- out = LayerNorm(x + r) * g + b ----------------------------
// 128 threads/row, exactly one float4 per thread (D=512).
__global__ __launch_bounds__(128)
void add_ln_kernel(const float4* __restrict__ x, const float4* __restrict__ r,
                   const float4* __restrict__ g, const float4* __restrict__ bb,
                   float4* __restrict__ out)
{
    int row = blockIdx.x;
    int tid = threadIdx.x;
    float4 xv = x[(size_t)row * 128 + tid];
    float4 rv = r[(size_t)row * 128 + tid];
    float4 v;
    v.x = xv.x + rv.x; v.y = xv.y + rv.y;
    v.z = xv.z + rv.z; v.w = xv.w + rv.w;
    float s1 = v.x + v.y + v.z + v.w;
    float s2 = v.x*v.x + v.y*v.y + v.z*v.z + v.w*v.w;
    #pragma unroll
    for (int off = 16; off; off >>= 1) {
        s1 += __shfl_xor_sync(0xffffffffu, s1, off);
        s2 += __shfl_xor_sync(0xffffffffu, s2, off);
    }
    __shared__ float w1[4], w2[4];
    int warp = tid >> 5, lane = tid & 31;
    if (lane == 0) { w1[warp] = s1; w2[warp] = s2; }
    __syncthreads();
    s1 = w1[0] + w1[1] + w1[2] + w1[3];
    s2 = w2[0] + w2[1] + w2[2] + w2[3];
    float mean = s1 * (1.f / Dq);
    float var  = s2 * (1.f / Dq) - mean * mean;
    float inv  = rsqrtf(var + 1e-5f);
    float4 gv = g[tid], bv = bb[tid];
    float4 o;
    o.x = (v.x - mean) * inv * gv.x + bv.x;
    o.y = (v.y - mean) * inv * gv.y + bv.y;
    o.z = (v.z - mean) * inv * gv.z + bv.z;
    o.w = (v.w - mean) * inv * gv.w + bv.w;
    out[(size_t)row * 128 + tid] = o;
}

// ---------------- orchestration ---------------------------------------------
extern "C" void kernel_launch(void* const* d_in, const int* in_sizes, int n_in,
                              void* d_out, int out_size)
{
    const float* q   = (const float*)d_in[0];
    const float* qa  = (const float*)d_in[1];
    const float* fr  = (const float*)d_in[2];
    const float* pos = (const float*)d_in[3];
    const float* Wk  = (const float*)d_in[4];
    const float* bk  = (const float*)d_in[5];
    const float* Wv  = (const float*)d_in[6];
    const float* bv  = (const float*)d_in[7];
    const float* Wo  = (const float*)d_in[8];
    const float* bo  = (const float*)d_in[9];
    const float* W1  = (const float*)d_in[10];
    const float* b1  = (const float*)d_in[11];
    const float* W2  = (const float*)d_in[12];
    const float* b2  = (const float*)d_in[13];
    const float* g1  = (const float*)d_in[14];
    const float* be1 = (const float*)d_in[15];
    const float* g2  = (const float*)d_in[16];
    const float* be2 = (const float*)d_in[17];
    float* out = (float*)d_out;

    float *xp, *yp, *kqp, *kqtp, *vp, *ctxp, *tp, *h1p;
    cudaGetSymbolAddress((void**)&xp,   g_x);
    cudaGetSymbolAddress((void**)&yp,   g_y);
    cudaGetSymbolAddress((void**)&kqp,  g_kq);
    cudaGetSymbolAddress((void**)&kqtp, g_kqt);
    cudaGetSymbolAddress((void**)&vp,   g_v);
    cudaGetSymbolAddress((void**)&ctxp, g_ctx);
    cudaGetSymbolAddress((void**)&tp,   g_tmp);
    cudaGetSymbolAddress((void**)&h1p,  g_h1);

    add_pos_kernel<<<Mq*Dq/4/256, 256>>>((const float4*)q, (const float4*)qa,
                                         (const float4*)pos,
                                         (float4*)xp, (float4*)yp);

    dim3 gD(Dq/128, Mq/128);   // 4 x 128
    dim3 gF(Fq/128, Mq/128);   // 16 x 128

    for (int l = 0; l < Lq; l++) {
        sgemm_tn<false><<<gD, 256>>>(xp, Wk + (size_t)l*Dq*Dq, bk + l*Dq, kqp, Mq, Dq, Dq);
        sgemm_tn<false><<<gD, 256>>>(yp, Wv + (size_t)l*Dq*Dq, bv + l*Dq, vp,  Mq, Dq, Dq);
        transpose_kq_kernel<<<dim3(Sq/32, DKq/32, Bq*Hq), dim3(32,8)>>>(kqp, kqtp);
        attn_kernel<<<dim3(Bq*Hq, ROWSPLIT), ATTN_WARPS*32>>>(kqp, kqtp, vp, fr, ctxp);
        sgemm_tn<false><<<gD, 256>>>(ctxp, Wo + (size_t)l*Dq*Dq, bo + l*Dq, tp, Mq, Dq, Dq);
        add_ln_kernel<<<Mq, 128>>>((const float4*)xp, (const float4*)tp,
                                   (const float4*)(g1 + l*Dq), (const float4*)(be1 + l*Dq),
                                   (float4*)xp);
        sgemm_tn<true ><<<gF, 256>>>(xp,  W1 + (size_t)l*Fq*Dq, b1 + l*Fq, h1p, Mq, Fq, Dq);
        sgemm_tn<false><<<gD, 256>>>(h1p, W2 + (size_t)l*Dq*Fq, b2 + l*Dq, tp,  Mq, Dq, Fq);
        float* o = (l == Lq-1) ? out : xp;
        add_ln_kernel<<<Mq, 128>>>((const float4*)xp, (const float4*)tp,
                                   (const float4*)(g2 + l*Dq), (const float4*)(be2 + l*Dq),
                                   (float4*)o);
    }
}

// round 13
// speedup vs baseline: 1.0036x; 1.0036x over previous
#include <cuda_runtime.h>
#include <math.h>
#include <stdint.h>

// Problem dims
#define Bq  32
#define Sq  512
#define Dq  512
#define Hq  8
#define Lq  4
#define Fq  2048
#define DKq 64
#define Mq  (Bq*Sq)   // 16384 rows

// ---------------- scratch (static __device__, no allocation) ----------------
__device__ float g_x  [Mq*Dq];
__device__ float g_y  [Mq*Dq];
__device__ float g_kq [Mq*Dq];
__device__ float g_kqt[Mq*Dq];   // (B,H,DK,S)
__device__ float g_v  [Mq*Dq];
__device__ float g_ctx[Mq*Dq];
__device__ float g_tmp[Mq*Dq];
__device__ float g_h1 [Mq*Fq];

// ---------------- x = q + pos ; y = qa + pos ----------------
__global__ void add_pos_kernel(const float4* __restrict__ q,
                               const float4* __restrict__ qa,
                               const float4* __restrict__ pos,
                               float4* __restrict__ x, float4* __restrict__ y)
{
    int i  = blockIdx.x * blockDim.x + threadIdx.x;   // Mq*Dq/4 total
    int pi = i & (Sq*Dq/4 - 1);                       // S*D/4 is pow2
    float4 p = pos[pi];
    float4 a = q[i];
    a.x += p.x; a.y += p.y; a.z += p.z; a.w += p.w;
    x[i] = a;
    float4 c = qa[i];
    c.x += p.x; c.y += p.y; c.z += p.z; c.w += p.w;
    y[i] = c;
}

// ---------------- TF32 helpers ----------------------------------------------
__device__ __forceinline__ float tf32_rna(float x) {
    uint32_t u;
    asm("cvt.rna.tf32.f32 %0, %1;" : "=r"(u) : "f"(x));
    return __uint_as_float(u);
}

__device__ __forceinline__ void mma_tf32(float* c,
    uint32_t a0, uint32_t a1, uint32_t a2, uint32_t a3,
    uint32_t b0, uint32_t b1)
{
    asm volatile(
        "mma.sync.aligned.m16n8k8.row.col.f32.tf32.tf32.f32 "
        "{%0,%1,%2,%3}, {%4,%5,%6,%7}, {%8,%9}, {%0,%1,%2,%3};"
        : "+f"(c[0]), "+f"(c[1]), "+f"(c[2]), "+f"(c[3])
        : "r"(a0), "r"(a1), "r"(a2), "r"(a3), "r"(b0), "r"(b1));
}

// ---------------- 3xTF32 GEMM: C[M,N] = A[M,K]*W[N,K]^T + bias (opt ReLU) ---
// BM=BN=128, BK=16, 256 threads = 8 warps (4x2), warp tile 32x64.
// hi/lo split of both operands; acc += ah*bh + ah*bl + al*bh (fp32 accum).
// smem m-major [128][BK+4]: fragment LDS conflict-free (stride 20: 20m mod 32
// covers all banks in steps of 4, +tig 0..3 fills each group).
// Requires M,N % 128 == 0, K % 16 == 0.
#define BKq 16
#define LDSM (BKq + 4)    // 20
template<bool RELU>
__global__ __launch_bounds__(256)
void gemm_tf32(const float* __restrict__ A, const float* __restrict__ W,
               const float* __restrict__ bias, float* __restrict__ C,
               int M, int N, int K)
{
    __shared__ float Ah[128][LDSM], Al[128][LDSM];
    __shared__ float Bh[128][LDSM], Bl[128][LDSM];

    const int tid   = threadIdx.x;
    const int bm    = blockIdx.y * 128;
    const int bn    = blockIdx.x * 128;
    const int warp  = tid >> 5;
    const int lane  = tid & 31;
    const int wm    = warp >> 1;        // 0..3 -> rows wm*32
    const int wn    = warp & 1;         // 0..1 -> cols wn*64
    const int gid   = lane >> 2;        // 0..7
    const int tig   = lane & 3;         // 0..3

    // loader mapping: each thread owns 8 consecutive k of one row
    const int lrow = tid >> 1;          // 0..127
    const int lkb  = (tid & 1) * 8;     // 0 or 8
    const float* Ag = A + (size_t)(bm + lrow) * K + lkb;
    const float* Wg = W + (size_t)(bn + lrow) * K + lkb;

    float acc[2][8][4];
    #pragma unroll
    for (int mt = 0; mt < 2; mt++)
        #pragma unroll
        for (int nt = 0; nt < 8; nt++)
            #pragma unroll
            for (int r = 0; r < 4; r++) acc[mt][nt][r] = 0.f;

    // prefetch k-tile 0
    float4 pa0 = *(const float4*)(Ag);
    float4 pa1 = *(const float4*)(Ag + 4);
    float4 pb0 = *(const float4*)(Wg);
    float4 pb1 = *(const float4*)(Wg + 4);

    for (int k0 = 0; k0 < K; k0 += BKq) {
        // split + store prefetched tile to smem
        {
            float va[8] = {pa0.x, pa0.y, pa0.z, pa0.w, pa1.x, pa1.y, pa1.z, pa1.w};
            float vb[8] = {pb0.x, pb0.y, pb0.z, pb0.w, pb1.x, pb1.y, pb1.z, pb1.w};
            float4 ah4, al4, bh4, bl4;
            float* pah = &ah4.x; float* pal = &al4.x;
            float* pbh = &bh4.x; float* pbl = &bl4.x;
            #pragma unroll
            for (int j = 0; j < 4; j++) {
                float h = tf32_rna(va[j]);       pah[j] = h; pal[j] = tf32_rna(va[j] - h);
                float hb = tf32_rna(vb[j]);      pbh[j] = hb; pbl[j] = tf32_rna(vb[j] - hb);
            }
            *(float4*)&Ah[lrow][lkb] = ah4;  *(float4*)&Al[lrow][lkb] = al4;
            *(float4*)&Bh[lrow][lkb] = bh4;  *(float4*)&Bl[lrow][lkb] = bl4;
            #pragma unroll
            for (int j = 0; j < 4; j++) {
                float h = tf32_rna(va[4+j]);     pah[j] = h; pal[j] = tf32_rna(va[4+j] - h);
                float hb = tf32_rna(vb[4+j]);    pbh[j] = hb; pbl[j] = tf32_rna(vb[4+j] - hb);
            }
            *(float4*)&Ah[lrow][lkb+4] = ah4; *(float4*)&Al[lrow][lkb+4] = al4;
            *(float4*)&Bh[lrow][lkb+4] = bh4; *(float4*)&Bl[lrow][lkb+4] = bl4;
        }
        __syncthreads();

        // prefetch next tile
        if (k0 + BKq < K) {
            pa0 = *(const float4*)(Ag + k0 + BKq);
            pa1 = *(const float4*)(Ag + k0 + BKq + 4);
            pb0 = *(const float4*)(Wg + k0 + BKq);
            pb1 = *(const float4*)(Wg + k0 + BKq + 4);
        }

        // compute 2 k8 sub-steps
        #pragma unroll
        for (int k8 = 0; k8 < 2; k8++) {
            const int kk = k8 * 8;
            uint32_t ah[2][4], al[2][4];
            #pragma unroll
            for (int mt = 0; mt < 2; mt++) {
                int rm = wm*32 + mt*16;
                ah[mt][0] = __float_as_uint(Ah[rm + gid    ][kk + tig    ]);
                ah[mt][1] = __float_as_uint(Ah[rm + gid + 8][kk + tig    ]);
                ah[mt][2] = __float_as_uint(Ah[rm + gid    ][kk + tig + 4]);
                ah[mt][3] = __float_as_uint(Ah[rm + gid + 8][kk + tig + 4]);
                al[mt][0] = __float_as_uint(Al[rm + gid    ][kk + tig    ]);
                al[mt][1] = __float_as_uint(Al[rm + gid + 8][kk + tig    ]);
                al[mt][2] = __float_as_uint(Al[rm + gid    ][kk + tig + 4]);
                al[mt][3] = __float_as_uint(Al[rm + gid + 8][kk + tig + 4]);
            }
            #pragma unroll
            for (int nt = 0; nt < 8; nt++) {
                int cn = wn*64 + nt*8 + gid;
                uint32_t bh0 = __float_as_uint(Bh[cn][kk + tig    ]);
                uint32_t bh1 = __float_as_uint(Bh[cn][kk + tig + 4]);
                uint32_t bl0 = __float_as_uint(Bl[cn][kk + tig    ]);
                uint32_t bl1 = __float_as_uint(Bl[cn][kk + tig + 4]);
                #pragma unroll
                for (int mt = 0; mt < 2; mt++) {
                    mma_tf32(acc[mt][nt], ah[mt][0], ah[mt][1], ah[mt][2], ah[mt][3], bh0, bh1);
                    mma_tf32(acc[mt][nt], ah[mt][0], ah[mt][1], ah[mt][2], ah[mt][3], bl0, bl1);
                    mma_tf32(acc[mt][nt], al[mt][0], al[mt][1], al[mt][2], al[mt][3], bh0, bh1);
                }
            }
        }
        __syncthreads();
    }

    // epilogue: bias + optional ReLU, float2 stores
    #pragma unroll
    for (int nt = 0; nt < 8; nt++) {
        int cb = bn + wn*64 + nt*8 + tig*2;
        float2 bb = *(const float2*)(bias + cb);
        #pragma unroll
        for (int mt = 0; mt < 2; mt++) {
            int r0 = bm + wm*32 + mt*16 + gid;
            float2 o0, o1;
            o0.x = acc[mt][nt][0] + bb.x; o0.y = acc[mt][nt][1] + bb.y;
            o1.x = acc[mt][nt][2] + bb.x; o1.y = acc[mt][nt][3] + bb.y;
            if (RELU) {
                o0.x = fmaxf(o0.x, 0.f); o0.y = fmaxf(o0.y, 0.f);
                o1.x = fmaxf(o1.x, 0.f); o1.y = fmaxf(o1.y, 0.f);
            }
            *(float2*)(C + (size_t)r0 * N + cb)       = o0;
            *(float2*)(C + (size_t)(r0 + 8) * N + cb) = o1;
        }
    }
}

// ---------------- transpose kq -> (B,H,DK,S) for coalesced key reads --------
__global__ void transpose_kq_kernel(const float* __restrict__ kq,
                                    float* __restrict__ kqt)
{
    __shared__ float tile[32][33];
    int bh = blockIdx.z;               // 0..B*H-1
    int dt = blockIdx.y;               // 0..DK/32-1
    int tt = blockIdx.x;               // 0..S/32-1
    int b = bh / Hq, h = bh % Hq;
    int tx = threadIdx.x;              // 32
    int ty = threadIdx.y;              // 8
    #pragma unroll
    for (int i = 0; i < 4; i++) {
        int t = tt*32 + ty + i*8;
        tile[ty + i*8][tx] = kq[((size_t)(b*Sq + t))*Dq + h*DKq + dt*32 + tx];
    }
    __syncthreads();
    #pragma unroll
    for (int i = 0; i < 4; i++) {
        int d = dt*32 + ty + i*8;
        kqt[((size_t)bh*DKq + d)*Sq + tt*32 + tx] = tile[tx][ty + i*8];
    }
}

// ---------------- two-pass strictly-causal attention ------------------------
#define ATTN_WARPS 8
#define ROWSPLIT   4
#define NBLK  (Sq/32)    // 16
__global__ __launch_bounds__(ATTN_WARPS*32)
void attn_kernel(const float* __restrict__ kq, const float* __restrict__ kqt,
                 const float* __restrict__ v, const float* __restrict__ fr,
                 float* __restrict__ ctx)
{
    __shared__ float qs_all[ATTN_WARPS][64];
    int warp = threadIdx.x >> 5;
    int lane = threadIdx.x & 31;
    int bh   = blockIdx.x;
    int b = bh / Hq, h = bh % Hq;
    float* qs = qs_all[warp];
    const float scale = 0.125f;                       // 1/sqrt(64)
    const size_t base  = ((size_t)b * Sq) * Dq + h * DKq;   // (b,*,h) in (B,S,D)
    const float* KT = kqt + (size_t)bh * DKq * Sq;          // (DK,S)

    int sstart = blockIdx.y * ATTN_WARPS + warp;
    for (int s = sstart; s < Sq; s += ATTN_WARPS * ROWSPLIT) {
        size_t orow = base + (size_t)s * Dq;
        if (s == 0) {
            ctx[orow + lane] = 0.f; ctx[orow + lane + 32] = 0.f;
            continue;
        }
        float qsc = scale * fr[b*Sq + s];
        qs[lane]      = kq[orow + lane]      * qsc;
        qs[lane + 32] = kq[orow + lane + 32] * qsc;
        __syncwarp();

        // ---- pass 1: scores into registers, lane-local max ----
        float preg[NBLK];
        float mymax = -3.0e38f;
        #pragma unroll
        for (int ib = 0; ib < NBLK; ib++) {
            int t0 = ib * 32;
            if (t0 >= s) break;
            int t = t0 + lane;
            float sc = -3.0e38f;
            if (t < s) {
                const float* KTt = KT + t;
                float a0 = 0.f, a1 = 0.f, a2 = 0.f, a3 = 0.f;
                #pragma unroll
                for (int d = 0; d < 64; d += 4) {
                    a0 += qs[d+0] * KTt[(size_t)(d+0)*Sq];
                    a1 += qs[d+1] * KTt[(size_t)(d+1)*Sq];
                    a2 += qs[d+2] * KTt[(size_t)(d+2)*Sq];
                    a3 += qs[d+3] * KTt[(size_t)(d+3)*Sq];
                }
                sc = (a0 + a1) + (a2 + a3);
            }
            preg[ib] = sc;
            mymax = fmaxf(mymax, sc);
        }
        #pragma unroll
        for (int off = 16; off; off >>= 1)
            mymax = fmaxf(mymax, __shfl_xor_sync(0xffffffffu, mymax, off));

        // ---- pass 2: exp + V accumulation ----
        float lsum = 0.f, o0 = 0.f, o1 = 0.f;
        #pragma unroll
        for (int ib = 0; ib < NBLK; ib++) {
            int t0 = ib * 32;
            if (t0 >= s) break;
            int t = t0 + lane;
            float p = (t < s) ? __expf(preg[ib] - mymax) : 0.f;
            lsum += p;
            int cnt = min(32, s - t0);
            const float* vb = v + base + (size_t)t0 * Dq;
            for (int tt = 0; tt < cnt; tt++) {
                float pt = __shfl_sync(0xffffffffu, p, tt);
                o0 += pt * vb[(size_t)tt * Dq + lane];
                o1 += pt * vb[(size_t)tt * Dq + lane + 32];
            }
        }
        #pragma unroll
        for (int off = 16; off; off >>= 1)
            lsum += __shfl_xor_sync(0xffffffffu, lsum, off);

        float inv = 1.f / lsum;
        ctx[orow + lane]      = o0 * inv;
        ctx[orow + lane + 32] = o1 * inv;
    }
}

// ---------------- out = LayerNorm(x + r) * g + b ----------------------------
__global__ __launch_bounds__(128)
void add_ln_kernel(const float4* __restrict__ x, const float4* __restrict__ r,
                   const float4* __restrict__ g, const float4* __restrict__ bb,
                   float4* __restrict__ out)
{
    int row = blockIdx.x;
    int tid = threadIdx.x;
    float4 xv = x[(size_t)row * 128 + tid];
    float4 rv = r[(size_t)row * 128 + tid];
    float4 v;
    v.x = xv.x + rv.x; v.y = xv.y + rv.y;
    v.z = xv.z + rv.z; v.w = xv.w + rv.w;
    float s1 = v.x + v.y + v.z + v.w;
    float s2 = v.x*v.x + v.y*v.y + v.z*v.z + v.w*v.w;
    #pragma unroll
    for (int off = 16; off; off >>= 1) {
        s1 += __shfl_xor_sync(0xffffffffu, s1, off);
        s2 += __shfl_xor_sync(0xffffffffu, s2, off);
    }
    __shared__ float w1[4], w2[4];
    int warp = tid >> 5, lane = tid & 31;
    if (lane == 0) { w1[warp] = s1; w2[warp] = s2; }
    __syncthreads();
    s1 = w1[0] + w1[1] + w1[2] + w1[3];
    s2 = w2[0] + w2[1] + w2[2] + w2[3];
    float mean = s1 * (1.f / Dq);
    float var  = s2 * (1.f / Dq) - mean * mean;
    float inv  = rsqrtf(var + 1e-5f);
    float4 gv = g[tid], bv = bb[tid];
    float4 o;
    o.x = (v.x - mean) * inv * gv.x + bv.x;
    o.y = (v.y - mean) * inv * gv.y + bv.y;
    o.z = (v.z - mean) * inv * gv.z + bv.z;
    o.w = (v.w - mean) * inv * gv.w + bv.w;
    out[(size_t)row * 128 + tid] = o;
}

// ---------------- orchestration ---------------------------------------------
extern "C" void kernel_launch(void* const* d_in, const int* in_sizes, int n_in,
                              void* d_out, int out_size)
{
    const float* q   = (const float*)d_in[0];
    const float* qa  = (const float*)d_in[1];
    const float* fr  = (const float*)d_in[2];
    const float* pos = (const float*)d_in[3];
    const float* Wk  = (const float*)d_in[4];
    const float* bk  = (const float*)d_in[5];
    const float* Wv  = (const float*)d_in[6];
    const float* bv  = (const float*)d_in[7];
    const float* Wo  = (const float*)d_in[8];
    const float* bo  = (const float*)d_in[9];
    const float* W1  = (const float*)d_in[10];
    const float* b1  = (const float*)d_in[11];
    const float* W2  = (const float*)d_in[12];
    const float* b2  = (const float*)d_in[13];
    const float* g1  = (const float*)d_in[14];
    const float* be1 = (const float*)d_in[15];
    const float* g2  = (const float*)d_in[16];
    const float* be2 = (const float*)d_in[17];
    float* out = (float*)d_out;

    float *xp, *yp, *kqp, *kqtp, *vp, *ctxp, *tp, *h1p;
    cudaGetSymbolAddress((void**)&xp,   g_x);
    cudaGetSymbolAddress((void**)&yp,   g_y);
    cudaGetSymbolAddress((void**)&kqp,  g_kq);
    cudaGetSymbolAddress((void**)&kqtp, g_kqt);
    cudaGetSymbolAddress((void**)&vp,   g_v);
    cudaGetSymbolAddress((void**)&ctxp, g_ctx);
    cudaGetSymbolAddress((void**)&tp,   g_tmp);
    cudaGetSymbolAddress((void**)&h1p,  g_h1);

    add_pos_kernel<<<Mq*Dq/4/256, 256>>>((const float4*)q, (const float4*)qa,
                                         (const float4*)pos,
                                         (float4*)xp, (float4*)yp);

    dim3 gD(Dq/128, Mq/128);   // 4 x 128
    dim3 gF(Fq/128, Mq/128);   // 16 x 128

    for (int l = 0; l < Lq; l++) {
        gemm_tf32<false><<<gD, 256>>>(xp, Wk + (size_t)l*Dq*Dq, bk + l*Dq, kqp, Mq, Dq, Dq);
        gemm_tf32<false><<<gD, 256>>>(yp, Wv + (size_t)l*Dq*Dq, bv + l*Dq, vp,  Mq, Dq, Dq);
        transpose_kq_kernel<<<dim3(Sq/32, DKq/32, Bq*Hq), dim3(32,8)>>>(kqp, kqtp);
        attn_kernel<<<dim3(Bq*Hq, ROWSPLIT), ATTN_WARPS*32>>>(kqp, kqtp, vp, fr, ctxp);
        gemm_tf32<false><<<gD, 256>>>(ctxp, Wo + (size_t)l*Dq*Dq, bo + l*Dq, tp, Mq, Dq, Dq);
        add_ln_kernel<<<Mq, 128>>>((const float4*)xp, (const float4*)tp,
                                   (const float4*)(g1 + l*Dq), (const float4*)(be1 + l*Dq),
                                   (float4*)xp);
        gemm_tf32<true ><<<gF, 256>>>(xp,  W1 + (size_t)l*Fq*Dq, b1 + l*Fq, h1p, Mq, Fq, Dq);
        gemm_tf32<false><<<gD, 256>>>(h1p, W2 + (size_t)l*Dq*Fq, b2 + l*Dq, tp,  Mq, Dq, Fq);
        float* o = (l == Lq-1) ? out : xp;
        add_ln_kernel<<<Mq, 128>>>((const float4*)xp, (const float4*)tp,
                                   (const float4*)(g2 + l*Dq), (const float4*)(be2 + l*Dq),
                                   (float4*)o);
    }
}